// round 8
// baseline (speedup 1.0000x reference)
#include <cuda_runtime.h>

#define ND 128
#define HID 16
#define N_MAX 100000

typedef unsigned long long u64;

// Device-global scratch; statically zeroed; each run restores its own state.
__device__ __align__(16) int   g_degi[N_MAX];    // reset by rcp_kernel
__device__ __align__(16) float g_invdeg[N_MAX];
__device__ __align__(16) float g_s[N_MAX];
__device__ float    g_acc;                       // reset by last edge_dot block
__device__ unsigned g_done;                      // wraps via atomicInc

// MLP parameters in constant memory (filled by D2D memcpy each call)
__constant__ float c_W1[ND * HID];
__constant__ float c_b1[HID];
__constant__ float c_W2[HID * HID];
__constant__ float c_b2[HID];
__constant__ float c_W3[HID * HID];
__constant__ float c_b3[HID];
__constant__ float c_Wc[HID];

#define FMA2(d, a, b) \
    asm("fma.rn.f32x2 %0, %1, %2, %3;" : "=l"(d) : "l"(a), "l"(b), "l"(d))
#define PACK2(d, s) \
    asm("mov.b64 %0, {%1, %1};" : "=l"(d) : "r"(__float_as_uint(s)))
#define UNPACK2(lo, hi, s) \
    asm("mov.b64 {%0, %1}, %2;" : "=r"(lo), "=r"(hi) : "l"(s))

__device__ __forceinline__ float ftanh(float v) {
    return 1.0f - __fdividef(2.0f, __expf(2.0f * v) + 1.0f);
}

// ---------------- deg scatter (stream 2) ----------------
#define DEG_TPB 256
#define DEG_EPT 4
__global__ void __launch_bounds__(DEG_TPB) deg_kernel(const int* __restrict__ esrc, int e) {
    long base = (long)(blockIdx.x * DEG_TPB + threadIdx.x) * DEG_EPT;
    if (base + DEG_EPT <= e) {
        int4 s4 = *(const int4*)(esrc + base);
        atomicAdd(&g_degi[s4.x], 1);
        atomicAdd(&g_degi[s4.y], 1);
        atomicAdd(&g_degi[s4.z], 1);
        atomicAdd(&g_degi[s4.w], 1);
    } else {
        for (long i = base; i < e; i++) atomicAdd(&g_degi[esrc[i]], 1);
    }
}

// ---------------- rcp (stream 2, after deg) ----------------
__global__ void rcp_kernel(int n) {
    int i = blockIdx.x * blockDim.x + threadIdx.x;
    if (i < n) {
        int d = g_degi[i];
        g_invdeg[i] = __frcp_rn((float)d);  // inf for d==0, never read
        g_degi[i] = 0;                       // restore for next replay
    }
}

// ---------------- MLP -> s (stream 1), weights from constant ----------------
#define MLP_TPB 128
#define MLP_NPT 2

__global__ void __launch_bounds__(MLP_TPB) mlp_kernel(const float* __restrict__ x, int n) {
    int tid = threadIdx.x;
    int node0 = blockIdx.x * (MLP_TPB * MLP_NPT) + tid;
    int node1 = node0 + MLP_TPB;
    int c0 = min(node0, n - 1);
    int c1 = min(node1, n - 1);

    const float4* xr0 = (const float4*)(x + (size_t)c0 * ND);
    const float4* xr1 = (const float4*)(x + (size_t)c1 * ND);

    const u64* cb1 = (const u64*)c_b1;
    u64 h0[8], h1v[8];
#pragma unroll
    for (int q = 0; q < 8; q++) { h0[q] = cb1[q]; h1v[q] = cb1[q]; }

    // layer 1: 128 -> 16, f32x2, 2 nodes/thread, weights via constant port
#pragma unroll 4
    for (int k4 = 0; k4 < ND / 4; k4++) {
        float4 xa = xr0[k4];
        float4 xb = xr1[k4];
        float xas[4] = {xa.x, xa.y, xa.z, xa.w};
        float xbs[4] = {xb.x, xb.y, xb.z, xb.w};
#pragma unroll
        for (int i = 0; i < 4; i++) {
            const ulonglong2* wr = (const ulonglong2*)(c_W1 + (k4 * 4 + i) * HID);
            u64 xpa, xpb;
            PACK2(xpa, xas[i]);
            PACK2(xpb, xbs[i]);
#pragma unroll
            for (int q = 0; q < 4; q++) {
                ulonglong2 ww = wr[q];
                FMA2(h0[2 * q],      xpa, ww.x);
                FMA2(h0[2 * q + 1],  xpa, ww.y);
                FMA2(h1v[2 * q],     xpb, ww.x);
                FMA2(h1v[2 * q + 1], xpb, ww.y);
            }
        }
    }

    float t0[HID], t1[HID];
#pragma unroll
    for (int q = 0; q < 8; q++) {
        unsigned lo, hi;
        UNPACK2(lo, hi, h0[q]);
        t0[2 * q] = ftanh(__uint_as_float(lo));
        t0[2 * q + 1] = ftanh(__uint_as_float(hi));
        UNPACK2(lo, hi, h1v[q]);
        t1[2 * q] = ftanh(__uint_as_float(lo));
        t1[2 * q + 1] = ftanh(__uint_as_float(hi));
    }

    // layer 2
    const u64* cb2 = (const u64*)c_b2;
    u64 a0[8], a1[8];
#pragma unroll
    for (int q = 0; q < 8; q++) { a0[q] = cb2[q]; a1[q] = cb2[q]; }
#pragma unroll
    for (int i = 0; i < HID; i++) {
        const ulonglong2* wr = (const ulonglong2*)(c_W2 + i * HID);
        u64 p0, p1;
        PACK2(p0, t0[i]);
        PACK2(p1, t1[i]);
#pragma unroll
        for (int q = 0; q < 4; q++) {
            ulonglong2 ww = wr[q];
            FMA2(a0[2 * q],     p0, ww.x);
            FMA2(a0[2 * q + 1], p0, ww.y);
            FMA2(a1[2 * q],     p1, ww.x);
            FMA2(a1[2 * q + 1], p1, ww.y);
        }
    }
#pragma unroll
    for (int q = 0; q < 8; q++) {
        unsigned lo, hi;
        UNPACK2(lo, hi, a0[q]);
        t0[2 * q] = ftanh(__uint_as_float(lo));
        t0[2 * q + 1] = ftanh(__uint_as_float(hi));
        UNPACK2(lo, hi, a1[q]);
        t1[2 * q] = ftanh(__uint_as_float(lo));
        t1[2 * q + 1] = ftanh(__uint_as_float(hi));
    }

    // layer 3
    const u64* cb3 = (const u64*)c_b3;
#pragma unroll
    for (int q = 0; q < 8; q++) { a0[q] = cb3[q]; a1[q] = cb3[q]; }
#pragma unroll
    for (int i = 0; i < HID; i++) {
        const ulonglong2* wr = (const ulonglong2*)(c_W3 + i * HID);
        u64 p0, p1;
        PACK2(p0, t0[i]);
        PACK2(p1, t1[i]);
#pragma unroll
        for (int q = 0; q < 4; q++) {
            ulonglong2 ww = wr[q];
            FMA2(a0[2 * q],     p0, ww.x);
            FMA2(a0[2 * q + 1], p0, ww.y);
            FMA2(a1[2 * q],     p1, ww.x);
            FMA2(a1[2 * q + 1], p1, ww.y);
        }
    }

    // tanh + contract with Wc -> scalar per node
    float s0 = 0.f, s1 = 0.f;
#pragma unroll
    for (int q = 0; q < 8; q++) {
        unsigned lo, hi;
        UNPACK2(lo, hi, a0[q]);
        s0 += ftanh(__uint_as_float(lo)) * c_Wc[2 * q];
        s0 += ftanh(__uint_as_float(hi)) * c_Wc[2 * q + 1];
        UNPACK2(lo, hi, a1[q]);
        s1 += ftanh(__uint_as_float(lo)) * c_Wc[2 * q];
        s1 += ftanh(__uint_as_float(hi)) * c_Wc[2 * q + 1];
    }
    // clamped duplicate writes carry identical values -> benign
    g_s[c0] = s0;
    g_s[c1] = s1;
}

// ---------------- edge dot + fused final sigmoid ----------------
#define E_TPB 256
#define E_EPT 8

__global__ void __launch_bounds__(E_TPB) edge_dot_kernel(
    const int* __restrict__ src, const int* __restrict__ dst,
    const float* __restrict__ bc, float* __restrict__ out,
    int e, float inv_n)
{
    __shared__ float sRed[E_TPB / 32];
    int tid = threadIdx.x;
    long base = (long)(blockIdx.x * E_TPB + tid) * E_EPT;
    float acc = 0.f;

    if (base + E_EPT <= e) {
        int4 sa = *(const int4*)(src + base);
        int4 sb = *(const int4*)(src + base + 4);
        int4 da = *(const int4*)(dst + base);
        int4 db = *(const int4*)(dst + base + 4);
        float w0 = __ldg(&g_invdeg[sa.x]), w1 = __ldg(&g_invdeg[sa.y]);
        float w2 = __ldg(&g_invdeg[sa.z]), w3 = __ldg(&g_invdeg[sa.w]);
        float w4 = __ldg(&g_invdeg[sb.x]), w5 = __ldg(&g_invdeg[sb.y]);
        float w6 = __ldg(&g_invdeg[sb.z]), w7 = __ldg(&g_invdeg[sb.w]);
        float v0 = __ldg(&g_s[da.x]), v1 = __ldg(&g_s[da.y]);
        float v2 = __ldg(&g_s[da.z]), v3 = __ldg(&g_s[da.w]);
        float v4 = __ldg(&g_s[db.x]), v5 = __ldg(&g_s[db.y]);
        float v6 = __ldg(&g_s[db.z]), v7 = __ldg(&g_s[db.w]);
        acc = fmaf(v0, w0, acc); acc = fmaf(v1, w1, acc);
        acc = fmaf(v2, w2, acc); acc = fmaf(v3, w3, acc);
        acc = fmaf(v4, w4, acc); acc = fmaf(v5, w5, acc);
        acc = fmaf(v6, w6, acc); acc = fmaf(v7, w7, acc);
    } else {
        for (long i = base; i < e; i++)
            acc += __ldg(&g_s[dst[i]]) * __ldg(&g_invdeg[src[i]]);
    }

    unsigned m = 0xffffffffu;
#pragma unroll
    for (int off = 16; off > 0; off >>= 1)
        acc += __shfl_down_sync(m, acc, off);
    if ((tid & 31) == 0) sRed[tid >> 5] = acc;
    __syncthreads();

    if (tid == 0) {
        float v = 0.f;
#pragma unroll
        for (int wq = 0; wq < E_TPB / 32; wq++) v += sRed[wq];
        atomicAdd(&g_acc, v);
        __threadfence();
        unsigned ticket = atomicInc(&g_done, gridDim.x - 1);  // wraps to 0 on last
        if (ticket == gridDim.x - 1) {
            float z = g_acc * inv_n + bc[0];
            out[0] = 1.0f / (1.0f + __expf(-z));
            g_acc = 0.f;  // restore for next replay
        }
    }
}

extern "C" void kernel_launch(void* const* d_in, const int* in_sizes, int n_in,
                              void* d_out, int out_size) {
    const float* x    = (const float*)d_in[0];
    const int*   esrc = (const int*)  d_in[1];
    const int*   edst = (const int*)  d_in[2];
    const float* W1   = (const float*)d_in[3];
    const float* b1   = (const float*)d_in[4];
    const float* W2   = (const float*)d_in[5];
    const float* b2   = (const float*)d_in[6];
    const float* W3   = (const float*)d_in[7];
    const float* b3   = (const float*)d_in[8];
    const float* Wc   = (const float*)d_in[9];
    const float* bc   = (const float*)d_in[10];
    float* out = (float*)d_out;

    int n = in_sizes[0] / ND;
    int e = in_sizes[1];
    if (n > N_MAX) n = N_MAX;

    // One-time resources (created on the uncaptured correctness run; reused
    // under capture; work per call is identical -> deterministic)
    static cudaStream_t s2 = 0;
    static cudaEvent_t evFork = 0, evJoin = 0;
    static int inited = 0;
    if (!inited) {
        cudaStreamCreateWithFlags(&s2, cudaStreamNonBlocking);
        cudaEventCreateWithFlags(&evFork, cudaEventDisableTiming);
        cudaEventCreateWithFlags(&evJoin, cudaEventDisableTiming);
        inited = 1;
    }

    // ---- fork: deg -> rcp on s2, concurrent with copies -> mlp on stream 0
    cudaEventRecord(evFork, 0);
    cudaStreamWaitEvent(s2, evFork, 0);

    int nDeg = (e + DEG_TPB * DEG_EPT - 1) / (DEG_TPB * DEG_EPT);
    deg_kernel<<<nDeg, DEG_TPB, 0, s2>>>(esrc, e);
    rcp_kernel<<<(n + 255) / 256, 256, 0, s2>>>(n);

    // constants for the MLP (D2D memcpy nodes on stream 0)
    cudaMemcpyToSymbolAsync(c_W1, W1, ND * HID * sizeof(float), 0, cudaMemcpyDeviceToDevice, 0);
    cudaMemcpyToSymbolAsync(c_b1, b1, HID * sizeof(float), 0, cudaMemcpyDeviceToDevice, 0);
    cudaMemcpyToSymbolAsync(c_W2, W2, HID * HID * sizeof(float), 0, cudaMemcpyDeviceToDevice, 0);
    cudaMemcpyToSymbolAsync(c_b2, b2, HID * sizeof(float), 0, cudaMemcpyDeviceToDevice, 0);
    cudaMemcpyToSymbolAsync(c_W3, W3, HID * HID * sizeof(float), 0, cudaMemcpyDeviceToDevice, 0);
    cudaMemcpyToSymbolAsync(c_b3, b3, HID * sizeof(float), 0, cudaMemcpyDeviceToDevice, 0);
    cudaMemcpyToSymbolAsync(c_Wc, Wc, HID * sizeof(float), 0, cudaMemcpyDeviceToDevice, 0);

    int nMlp = (n + MLP_TPB * MLP_NPT - 1) / (MLP_TPB * MLP_NPT);
    mlp_kernel<<<nMlp, MLP_TPB>>>(x, n);

    // ---- join, then edge contraction + output
    cudaEventRecord(evJoin, s2);
    cudaStreamWaitEvent(0, evJoin, 0);

    int nEdge = (e + E_TPB * E_EPT - 1) / (E_TPB * E_EPT);
    edge_dot_kernel<<<nEdge, E_TPB>>>(esrc, edst, bc, out, e, 1.0f / (float)n);
}

// round 9
// speedup vs baseline: 1.1816x; 1.1816x over previous
#include <cuda_runtime.h>

#define ND 128
#define HID 16
#define N_MAX 100000

typedef unsigned long long u64;

// Device-global scratch; statically zeroed; each run restores its own state
// so graph replays see identical initial conditions.
__device__ __align__(16) double g_ud[N_MAX];   // cnt*2^24 + sum(s); reset by node_kernel
__device__ __align__(16) float  g_s[N_MAX];
__device__ float    g_acc;                     // reset by last node_kernel block
__device__ unsigned g_done;                    // wraps via atomicInc

#define FMA2(d, a, b) \
    asm("fma.rn.f32x2 %0, %1, %2, %3;" : "=l"(d) : "l"(a), "l"(b), "l"(d))
#define PACK2(d, s) \
    asm("mov.b64 %0, {%1, %1};" : "=l"(d) : "r"(__float_as_uint(s)))
#define UNPACK2(lo, hi, s) \
    asm("mov.b64 {%0, %1}, %2;" : "=r"(lo), "=r"(hi) : "l"(s))

__device__ __forceinline__ float ftanh(float v) {
    return 1.0f - __fdividef(2.0f, __expf(2.0f * v) + 1.0f);
}

// ---------------- K1: MLP -> s (smem weights, f32x2, 1 node/thread) --------
#define MLP_TPB 256

__global__ void __launch_bounds__(MLP_TPB) mlp_kernel(
    const float* __restrict__ x,
    const float* __restrict__ W1, const float* __restrict__ b1,
    const float* __restrict__ W2, const float* __restrict__ b2,
    const float* __restrict__ W3, const float* __restrict__ b3,
    const float* __restrict__ Wc,
    int n)
{
    __shared__ float4 sW1[ND * HID / 4];   // 8KB
    __shared__ float4 sW2[HID * HID / 4];
    __shared__ float4 sW3[HID * HID / 4];
    __shared__ u64 sb1[8], sb2[8], sb3[8];
    __shared__ float sWc[HID];

    int tid = threadIdx.x;
    for (int i = tid; i < ND * HID / 4; i += MLP_TPB) sW1[i] = ((const float4*)W1)[i];
    if (tid < HID * HID / 4) {
        sW2[tid] = ((const float4*)W2)[tid];
        sW3[tid] = ((const float4*)W3)[tid];
    }
    if (tid < 8) {
        sb1[tid] = ((const u64*)b1)[tid];
        sb2[tid] = ((const u64*)b2)[tid];
        sb3[tid] = ((const u64*)b3)[tid];
    }
    if (tid < HID) sWc[tid] = Wc[tid];
    __syncthreads();

    int node = blockIdx.x * MLP_TPB + tid;
    int c0 = min(node, n - 1);
    const float4* xr = (const float4*)(x + (size_t)c0 * ND);

    u64 h[8];
#pragma unroll
    for (int q = 0; q < 8; q++) h[q] = sb1[q];

    // layer 1: 128 -> 16, f32x2 packed
#pragma unroll 8
    for (int k4 = 0; k4 < ND / 4; k4++) {
        float4 xv = xr[k4];
        float xs[4] = {xv.x, xv.y, xv.z, xv.w};
#pragma unroll
        for (int i = 0; i < 4; i++) {
            const ulonglong2* wr = (const ulonglong2*)(sW1 + (k4 * 4 + i) * 4);
            u64 xp;
            PACK2(xp, xs[i]);
#pragma unroll
            for (int q = 0; q < 4; q++) {
                ulonglong2 ww = wr[q];
                FMA2(h[2 * q],     xp, ww.x);
                FMA2(h[2 * q + 1], xp, ww.y);
            }
        }
    }

    float t0[HID];
#pragma unroll
    for (int q = 0; q < 8; q++) {
        unsigned lo, hi;
        UNPACK2(lo, hi, h[q]);
        t0[2 * q]     = ftanh(__uint_as_float(lo));
        t0[2 * q + 1] = ftanh(__uint_as_float(hi));
    }

    // layer 2
    u64 a0[8];
#pragma unroll
    for (int q = 0; q < 8; q++) a0[q] = sb2[q];
#pragma unroll
    for (int i = 0; i < HID; i++) {
        const ulonglong2* wr = (const ulonglong2*)(sW2 + i * 4);
        u64 p0;
        PACK2(p0, t0[i]);
#pragma unroll
        for (int q = 0; q < 4; q++) {
            ulonglong2 ww = wr[q];
            FMA2(a0[2 * q],     p0, ww.x);
            FMA2(a0[2 * q + 1], p0, ww.y);
        }
    }
#pragma unroll
    for (int q = 0; q < 8; q++) {
        unsigned lo, hi;
        UNPACK2(lo, hi, a0[q]);
        t0[2 * q]     = ftanh(__uint_as_float(lo));
        t0[2 * q + 1] = ftanh(__uint_as_float(hi));
    }

    // layer 3
#pragma unroll
    for (int q = 0; q < 8; q++) a0[q] = sb3[q];
#pragma unroll
    for (int i = 0; i < HID; i++) {
        const ulonglong2* wr = (const ulonglong2*)(sW3 + i * 4);
        u64 p0;
        PACK2(p0, t0[i]);
#pragma unroll
        for (int q = 0; q < 4; q++) {
            ulonglong2 ww = wr[q];
            FMA2(a0[2 * q],     p0, ww.x);
            FMA2(a0[2 * q + 1], p0, ww.y);
        }
    }

    // tanh + contract with Wc -> scalar per node
    float s0 = 0.f;
#pragma unroll
    for (int q = 0; q < 8; q++) {
        unsigned lo, hi;
        UNPACK2(lo, hi, a0[q]);
        s0 += ftanh(__uint_as_float(lo)) * sWc[2 * q];
        s0 += ftanh(__uint_as_float(hi)) * sWc[2 * q + 1];
    }
    // clamped duplicate writes carry identical values -> benign
    g_s[c0] = s0;
}

// ------ K2: single edge pass: ud[src] += s[dst] + 2^24 (one REDG.64) ------
#define E_TPB 256
#define E_EPT 8
#define CNT_K 16777216.0   // 2^24

__global__ void __launch_bounds__(E_TPB) edge_kernel(
    const int* __restrict__ src, const int* __restrict__ dst, int e)
{
    long base = (long)(blockIdx.x * E_TPB + threadIdx.x) * E_EPT;
    if (base + E_EPT <= e) {
        int4 da = *(const int4*)(dst + base);
        int4 db = *(const int4*)(dst + base + 4);
        int4 sa = *(const int4*)(src + base);
        int4 sb = *(const int4*)(src + base + 4);
        // issue all gathers first (deep MLP), then fire-and-forget REDs
        float v0 = __ldg(&g_s[da.x]), v1 = __ldg(&g_s[da.y]);
        float v2 = __ldg(&g_s[da.z]), v3 = __ldg(&g_s[da.w]);
        float v4 = __ldg(&g_s[db.x]), v5 = __ldg(&g_s[db.y]);
        float v6 = __ldg(&g_s[db.z]), v7 = __ldg(&g_s[db.w]);
        atomicAdd(&g_ud[sa.x], (double)v0 + CNT_K);
        atomicAdd(&g_ud[sa.y], (double)v1 + CNT_K);
        atomicAdd(&g_ud[sa.z], (double)v2 + CNT_K);
        atomicAdd(&g_ud[sa.w], (double)v3 + CNT_K);
        atomicAdd(&g_ud[sb.x], (double)v4 + CNT_K);
        atomicAdd(&g_ud[sb.y], (double)v5 + CNT_K);
        atomicAdd(&g_ud[sb.z], (double)v6 + CNT_K);
        atomicAdd(&g_ud[sb.w], (double)v7 + CNT_K);
    } else {
        for (long i = base; i < e; i++)
            atomicAdd(&g_ud[src[i]], (double)__ldg(&g_s[dst[i]]) + CNT_K);
    }
}

// ------ K3: node pass: acc = sum_m u[m]/cnt[m]; sigmoid; reset state ------
#define N_TPB 256

__global__ void __launch_bounds__(N_TPB) node_kernel(
    const float* __restrict__ bc, float* __restrict__ out, int n, float inv_n)
{
    __shared__ float sRed[N_TPB / 32];
    int tid = threadIdx.x;
    int i = blockIdx.x * N_TPB + tid;
    float term = 0.f;

    if (i < n) {
        double v = g_ud[i];
        if (v != 0.0) {
            // cnt = round(v / 2^24); |sum(s)| < 2^23 so rounding recovers cnt exactly
            long long cnt = __double2ll_rn(v * (1.0 / CNT_K));
            float u = (float)(v - (double)cnt * CNT_K);
            term = u * __frcp_rn((float)cnt);
            g_ud[i] = 0.0;  // restore for next graph replay
        }
    }

    unsigned m = 0xffffffffu;
#pragma unroll
    for (int off = 16; off > 0; off >>= 1)
        term += __shfl_down_sync(m, term, off);
    if ((tid & 31) == 0) sRed[tid >> 5] = term;
    __syncthreads();

    if (tid == 0) {
        float v = 0.f;
#pragma unroll
        for (int wq = 0; wq < N_TPB / 32; wq++) v += sRed[wq];
        atomicAdd(&g_acc, v);
        __threadfence();
        unsigned ticket = atomicInc(&g_done, gridDim.x - 1);  // wraps to 0 on last
        if (ticket == gridDim.x - 1) {
            float z = g_acc * inv_n + bc[0];
            out[0] = 1.0f / (1.0f + __expf(-z));
            g_acc = 0.f;  // restore for next replay
        }
    }
}

extern "C" void kernel_launch(void* const* d_in, const int* in_sizes, int n_in,
                              void* d_out, int out_size) {
    const float* x    = (const float*)d_in[0];
    const int*   esrc = (const int*)  d_in[1];
    const int*   edst = (const int*)  d_in[2];
    const float* W1   = (const float*)d_in[3];
    const float* b1   = (const float*)d_in[4];
    const float* W2   = (const float*)d_in[5];
    const float* b2   = (const float*)d_in[6];
    const float* W3   = (const float*)d_in[7];
    const float* b3   = (const float*)d_in[8];
    const float* Wc   = (const float*)d_in[9];
    const float* bc   = (const float*)d_in[10];
    float* out = (float*)d_out;

    int n = in_sizes[0] / ND;
    int e = in_sizes[1];
    if (n > N_MAX) n = N_MAX;

    int nMlp = (n + MLP_TPB - 1) / MLP_TPB;
    mlp_kernel<<<nMlp, MLP_TPB>>>(x, W1, b1, W2, b2, W3, b3, Wc, n);

    int nEdge = (e + E_TPB * E_EPT - 1) / (E_TPB * E_EPT);
    edge_kernel<<<nEdge, E_TPB>>>(esrc, edst, e);

    int nNode = (n + N_TPB - 1) / N_TPB;
    node_kernel<<<nNode, N_TPB>>>(bc, out, n, 1.0f / (float)n);
}

// round 10
// speedup vs baseline: 1.3551x; 1.1469x over previous
#include <cuda_runtime.h>

#define ND 128
#define HID 16
#define N_MAX 100000

typedef unsigned long long u64;

// Device-global scratch; statically zeroed; each run restores its own state
// so graph replays see identical initial conditions.
__device__ __align__(16) double g_ud[N_MAX];   // cnt*2^24 + sum(s); reset by node_kernel
__device__ __align__(16) float  g_s[N_MAX];
__device__ float    g_acc;                     // reset by last node_kernel block
__device__ unsigned g_done;                    // wraps via atomicInc

#define FMA2(d, a, b) \
    asm("fma.rn.f32x2 %0, %1, %2, %3;" : "=l"(d) : "l"(a), "l"(b), "l"(d))
#define PACK2(d, s) \
    asm("mov.b64 %0, {%1, %1};" : "=l"(d) : "r"(__float_as_uint(s)))
#define UNPACK2(lo, hi, s) \
    asm("mov.b64 {%0, %1}, %2;" : "=r"(lo), "=r"(hi) : "l"(s))

__device__ __forceinline__ float ftanh(float v) {
    return 1.0f - __fdividef(2.0f, __expf(2.0f * v) + 1.0f);
}

// ---------------- K1: MLP -> s, smem-staged x, NPT=2 ----------------------
#define MLP_TPB 128
#define MLP_NPT 2                 // 256 nodes per block
#define NB (MLP_TPB * MLP_NPT)    // 256
#define KT 8                      // 8 k-tiles of 16 floats (4 float4)

__global__ void __launch_bounds__(MLP_TPB) mlp_kernel(
    const float* __restrict__ x,
    const float* __restrict__ W1, const float* __restrict__ b1,
    const float* __restrict__ W2, const float* __restrict__ b2,
    const float* __restrict__ W3, const float* __restrict__ b3,
    const float* __restrict__ Wc,
    int n)
{
    __shared__ float4 sX[NB * 5];          // 256 rows x (4 float4 + 1 pad) = 20.5KB
    __shared__ float4 sW1[ND * HID / 4];   // 8KB
    __shared__ float4 sW2[HID * HID / 4];
    __shared__ float4 sW3[HID * HID / 4];
    __shared__ u64 sb1[8], sb2[8], sb3[8];
    __shared__ float sWc[HID];

    int tid = threadIdx.x;
    for (int i = tid; i < ND * HID / 4; i += MLP_TPB) sW1[i] = ((const float4*)W1)[i];
    if (tid < HID * HID / 4) {
        sW2[tid] = ((const float4*)W2)[tid];
        sW3[tid] = ((const float4*)W3)[tid];
    }
    if (tid < 8) {
        sb1[tid] = ((const u64*)b1)[tid];
        sb2[tid] = ((const u64*)b2)[tid];
        sb3[tid] = ((const u64*)b3)[tid];
    }
    if (tid < HID) sWc[tid] = Wc[tid];

    int nodeBase = blockIdx.x * NB;
    // my two rows in the tile
    int r0 = tid, r1 = tid + MLP_TPB;
    int myN0 = min(nodeBase + r0, n - 1);
    int myN1 = min(nodeBase + r1, n - 1);

    // cooperative-load coordinates (fixed across tiles): 8 float4 per thread
    int lr[8], lj[8];
    const float4* lg[8];
#pragma unroll
    for (int i = 0; i < 8; i++) {
        int lin = i * MLP_TPB + tid;
        lr[i] = lin >> 2;
        lj[i] = lin & 3;
        int gn = min(nodeBase + lr[i], n - 1);
        lg[i] = ((const float4*)(x + (size_t)gn * ND)) + lj[i];
    }

    u64 h0[8], h1v[8];

    __syncthreads();  // weights + biases visible
#pragma unroll
    for (int q = 0; q < 8; q++) { h0[q] = sb1[q]; h1v[q] = sb1[q]; }

    // ---- layer 1 over 8 k-tiles of 16 floats ----
#pragma unroll
    for (int kt = 0; kt < KT; kt++) {
        float4 v[8];
#pragma unroll
        for (int i = 0; i < 8; i++) v[i] = lg[i][kt * 4];  // coalesced-ish, 8 lines/warp

        if (kt > 0) __syncthreads();  // previous tile fully consumed
#pragma unroll
        for (int i = 0; i < 8; i++) sX[lr[i] * 5 + lj[i]] = v[i];
        __syncthreads();

#pragma unroll
        for (int j = 0; j < 4; j++) {
            float4 xa = sX[r0 * 5 + j];
            float4 xb = sX[r1 * 5 + j];
            float xas[4] = {xa.x, xa.y, xa.z, xa.w};
            float xbs[4] = {xb.x, xb.y, xb.z, xb.w};
#pragma unroll
            for (int i = 0; i < 4; i++) {
                int k = kt * 16 + j * 4 + i;
                const ulonglong2* wr = (const ulonglong2*)(sW1 + k * 4);
                u64 xpa, xpb;
                PACK2(xpa, xas[i]);
                PACK2(xpb, xbs[i]);
#pragma unroll
                for (int q = 0; q < 4; q++) {
                    ulonglong2 ww = wr[q];
                    FMA2(h0[2 * q],      xpa, ww.x);
                    FMA2(h0[2 * q + 1],  xpa, ww.y);
                    FMA2(h1v[2 * q],     xpb, ww.x);
                    FMA2(h1v[2 * q + 1], xpb, ww.y);
                }
            }
        }
    }

    float t0[HID], t1[HID];
#pragma unroll
    for (int q = 0; q < 8; q++) {
        unsigned lo, hi;
        UNPACK2(lo, hi, h0[q]);
        t0[2 * q] = ftanh(__uint_as_float(lo));
        t0[2 * q + 1] = ftanh(__uint_as_float(hi));
        UNPACK2(lo, hi, h1v[q]);
        t1[2 * q] = ftanh(__uint_as_float(lo));
        t1[2 * q + 1] = ftanh(__uint_as_float(hi));
    }

    // ---- layer 2 ----
    u64 a0[8], a1[8];
#pragma unroll
    for (int q = 0; q < 8; q++) { a0[q] = sb2[q]; a1[q] = sb2[q]; }
#pragma unroll
    for (int i = 0; i < HID; i++) {
        const ulonglong2* wr = (const ulonglong2*)(sW2 + i * 4);
        u64 p0, p1;
        PACK2(p0, t0[i]);
        PACK2(p1, t1[i]);
#pragma unroll
        for (int q = 0; q < 4; q++) {
            ulonglong2 ww = wr[q];
            FMA2(a0[2 * q],     p0, ww.x);
            FMA2(a0[2 * q + 1], p0, ww.y);
            FMA2(a1[2 * q],     p1, ww.x);
            FMA2(a1[2 * q + 1], p1, ww.y);
        }
    }
#pragma unroll
    for (int q = 0; q < 8; q++) {
        unsigned lo, hi;
        UNPACK2(lo, hi, a0[q]);
        t0[2 * q] = ftanh(__uint_as_float(lo));
        t0[2 * q + 1] = ftanh(__uint_as_float(hi));
        UNPACK2(lo, hi, a1[q]);
        t1[2 * q] = ftanh(__uint_as_float(lo));
        t1[2 * q + 1] = ftanh(__uint_as_float(hi));
    }

    // ---- layer 3 ----
#pragma unroll
    for (int q = 0; q < 8; q++) { a0[q] = sb3[q]; a1[q] = sb3[q]; }
#pragma unroll
    for (int i = 0; i < HID; i++) {
        const ulonglong2* wr = (const ulonglong2*)(sW3 + i * 4);
        u64 p0, p1;
        PACK2(p0, t0[i]);
        PACK2(p1, t1[i]);
#pragma unroll
        for (int q = 0; q < 4; q++) {
            ulonglong2 ww = wr[q];
            FMA2(a0[2 * q],     p0, ww.x);
            FMA2(a0[2 * q + 1], p0, ww.y);
            FMA2(a1[2 * q],     p1, ww.x);
            FMA2(a1[2 * q + 1], p1, ww.y);
        }
    }

    // tanh + contract with Wc -> scalar per node
    float s0 = 0.f, s1 = 0.f;
#pragma unroll
    for (int q = 0; q < 8; q++) {
        unsigned lo, hi;
        UNPACK2(lo, hi, a0[q]);
        s0 += ftanh(__uint_as_float(lo)) * sWc[2 * q];
        s0 += ftanh(__uint_as_float(hi)) * sWc[2 * q + 1];
        UNPACK2(lo, hi, a1[q]);
        s1 += ftanh(__uint_as_float(lo)) * sWc[2 * q];
        s1 += ftanh(__uint_as_float(hi)) * sWc[2 * q + 1];
    }
    // clamped duplicate writes carry identical values -> benign
    g_s[myN0] = s0;
    g_s[myN1] = s1;
}

// ------ K2: single edge pass: ud[src] += s[dst] + 2^24 (one REDG.64) ------
#define E_TPB 256
#define E_EPT 8
#define CNT_K 16777216.0   // 2^24

__global__ void __launch_bounds__(E_TPB) edge_kernel(
    const int* __restrict__ src, const int* __restrict__ dst, int e)
{
    long base = (long)(blockIdx.x * E_TPB + threadIdx.x) * E_EPT;
    if (base + E_EPT <= e) {
        int4 da = *(const int4*)(dst + base);
        int4 db = *(const int4*)(dst + base + 4);
        int4 sa = *(const int4*)(src + base);
        int4 sb = *(const int4*)(src + base + 4);
        float v0 = __ldg(&g_s[da.x]), v1 = __ldg(&g_s[da.y]);
        float v2 = __ldg(&g_s[da.z]), v3 = __ldg(&g_s[da.w]);
        float v4 = __ldg(&g_s[db.x]), v5 = __ldg(&g_s[db.y]);
        float v6 = __ldg(&g_s[db.z]), v7 = __ldg(&g_s[db.w]);
        atomicAdd(&g_ud[sa.x], (double)v0 + CNT_K);
        atomicAdd(&g_ud[sa.y], (double)v1 + CNT_K);
        atomicAdd(&g_ud[sa.z], (double)v2 + CNT_K);
        atomicAdd(&g_ud[sa.w], (double)v3 + CNT_K);
        atomicAdd(&g_ud[sb.x], (double)v4 + CNT_K);
        atomicAdd(&g_ud[sb.y], (double)v5 + CNT_K);
        atomicAdd(&g_ud[sb.z], (double)v6 + CNT_K);
        atomicAdd(&g_ud[sb.w], (double)v7 + CNT_K);
    } else {
        for (long i = base; i < e; i++)
            atomicAdd(&g_ud[src[i]], (double)__ldg(&g_s[dst[i]]) + CNT_K);
    }
}

// ------ K3: node pass: acc = sum_m u[m]/cnt[m]; sigmoid; reset state ------
#define N_TPB 256

__global__ void __launch_bounds__(N_TPB) node_kernel(
    const float* __restrict__ bc, float* __restrict__ out, int n, float inv_n)
{
    __shared__ float sRed[N_TPB / 32];
    int tid = threadIdx.x;
    int i = blockIdx.x * N_TPB + tid;
    float term = 0.f;

    if (i < n) {
        double v = g_ud[i];
        if (v != 0.0) {
            // cnt = round(v / 2^24); |sum(s)| < 2^23 so rounding recovers cnt exactly
            long long cnt = __double2ll_rn(v * (1.0 / CNT_K));
            float u = (float)(v - (double)cnt * CNT_K);
            term = u * __frcp_rn((float)cnt);
            g_ud[i] = 0.0;  // restore for next graph replay
        }
    }

    unsigned m = 0xffffffffu;
#pragma unroll
    for (int off = 16; off > 0; off >>= 1)
        term += __shfl_down_sync(m, term, off);
    if ((tid & 31) == 0) sRed[tid >> 5] = term;
    __syncthreads();

    if (tid == 0) {
        float v = 0.f;
#pragma unroll
        for (int wq = 0; wq < N_TPB / 32; wq++) v += sRed[wq];
        atomicAdd(&g_acc, v);
        __threadfence();
        unsigned ticket = atomicInc(&g_done, gridDim.x - 1);  // wraps to 0 on last
        if (ticket == gridDim.x - 1) {
            float z = g_acc * inv_n + bc[0];
            out[0] = 1.0f / (1.0f + __expf(-z));
            g_acc = 0.f;  // restore for next replay
        }
    }
}

extern "C" void kernel_launch(void* const* d_in, const int* in_sizes, int n_in,
                              void* d_out, int out_size) {
    const float* x    = (const float*)d_in[0];
    const int*   esrc = (const int*)  d_in[1];
    const int*   edst = (const int*)  d_in[2];
    const float* W1   = (const float*)d_in[3];
    const float* b1   = (const float*)d_in[4];
    const float* W2   = (const float*)d_in[5];
    const float* b2   = (const float*)d_in[6];
    const float* W3   = (const float*)d_in[7];
    const float* b3   = (const float*)d_in[8];
    const float* Wc   = (const float*)d_in[9];
    const float* bc   = (const float*)d_in[10];
    float* out = (float*)d_out;

    int n = in_sizes[0] / ND;
    int e = in_sizes[1];
    if (n > N_MAX) n = N_MAX;

    int nMlp = (n + NB - 1) / NB;
    mlp_kernel<<<nMlp, MLP_TPB>>>(x, W1, b1, W2, b2, W3, b3, Wc, n);

    int nEdge = (e + E_TPB * E_EPT - 1) / (E_TPB * E_EPT);
    edge_kernel<<<nEdge, E_TPB>>>(esrc, edst, e);

    int nNode = (n + N_TPB - 1) / N_TPB;
    node_kernel<<<nNode, N_TPB>>>(bc, out, n, 1.0f / (float)n);
}

// round 11
// speedup vs baseline: 1.3645x; 1.0069x over previous
#include <cuda_runtime.h>

#define ND 128
#define HID 16
#define N_MAX 100000

typedef unsigned long long u64;

// Device-global scratch; statically zeroed; each run restores its own state
// so graph replays see identical initial conditions.
__device__ __align__(16) double g_ud[N_MAX];   // cnt*2^24 + sum(s); reset by node_kernel
__device__ __align__(16) float  g_s[N_MAX];
__device__ float    g_acc;                     // reset by last node_kernel block
__device__ unsigned g_done;                    // wraps via atomicInc

#define FMA2(d, a, b) \
    asm("fma.rn.f32x2 %0, %1, %2, %3;" : "=l"(d) : "l"(a), "l"(b), "l"(d))
#define PACK2(d, s) \
    asm("mov.b64 %0, {%1, %1};" : "=l"(d) : "r"(__float_as_uint(s)))
#define UNPACK2(lo, hi, s) \
    asm("mov.b64 {%0, %1}, %2;" : "=r"(lo), "=r"(hi) : "l"(s))

__device__ __forceinline__ float ftanh(float v) {
    return 1.0f - __fdividef(2.0f, __expf(2.0f * v) + 1.0f);
}

// ---------------- K1: MLP -> s, pipelined smem-staged x, NPT=2 -------------
#define MLP_TPB 128
#define MLP_NPT 2                 // 256 nodes per block
#define NB (MLP_TPB * MLP_NPT)    // 256
#define KT 8                      // 8 k-tiles of 16 floats (4 float4)

__global__ void __launch_bounds__(MLP_TPB) mlp_kernel(
    const float* __restrict__ x,
    const float* __restrict__ W1, const float* __restrict__ b1,
    const float* __restrict__ W2, const float* __restrict__ b2,
    const float* __restrict__ W3, const float* __restrict__ b3,
    const float* __restrict__ Wc,
    int n)
{
    __shared__ float4 sX[NB * 5];          // 256 rows x (4 float4 + 1 pad) = 20.5KB
    __shared__ float4 sW1[ND * HID / 4];   // 8KB
    __shared__ float4 sW2[HID * HID / 4];
    __shared__ float4 sW3[HID * HID / 4];
    __shared__ u64 sb1[8], sb2[8], sb3[8];
    __shared__ float sWc[HID];

    int tid = threadIdx.x;
    for (int i = tid; i < ND * HID / 4; i += MLP_TPB) sW1[i] = ((const float4*)W1)[i];
    if (tid < HID * HID / 4) {
        sW2[tid] = ((const float4*)W2)[tid];
        sW3[tid] = ((const float4*)W3)[tid];
    }
    if (tid < 8) {
        sb1[tid] = ((const u64*)b1)[tid];
        sb2[tid] = ((const u64*)b2)[tid];
        sb3[tid] = ((const u64*)b3)[tid];
    }
    if (tid < HID) sWc[tid] = Wc[tid];

    int nodeBase = blockIdx.x * NB;
    // my two rows in the tile
    int r0 = tid, r1 = tid + MLP_TPB;
    int myN0 = min(nodeBase + r0, n - 1);
    int myN1 = min(nodeBase + r1, n - 1);

    // cooperative-load coordinates (fixed across tiles): 8 float4 per thread
    int lr[8], lj[8];
    const float4* lg[8];
#pragma unroll
    for (int i = 0; i < 8; i++) {
        int lin = i * MLP_TPB + tid;
        lr[i] = lin >> 2;
        lj[i] = lin & 3;
        int gn = min(nodeBase + lr[i], n - 1);
        lg[i] = ((const float4*)(x + (size_t)gn * ND)) + lj[i];
    }

    u64 h0[8], h1v[8];

    // prologue: issue loads for tile 0 (no wait yet)
    float4 v[8];
#pragma unroll
    for (int i = 0; i < 8; i++) v[i] = lg[i][0];

    __syncthreads();  // weights + biases visible
#pragma unroll
    for (int q = 0; q < 8; q++) { h0[q] = sb1[q]; h1v[q] = sb1[q]; }

    // ---- layer 1 over 8 k-tiles of 16 floats, software-pipelined ----
#pragma unroll
    for (int kt = 0; kt < KT; kt++) {
        if (kt > 0) __syncthreads();  // previous tile fully consumed by all
#pragma unroll
        for (int i = 0; i < 8; i++) sX[lr[i] * 5 + lj[i]] = v[i];  // waits on v
        __syncthreads();

        // issue next tile's loads NOW; latency hidden behind this tile's FMAs
        if (kt + 1 < KT) {
#pragma unroll
            for (int i = 0; i < 8; i++) v[i] = lg[i][(kt + 1) * 4];
        }

#pragma unroll
        for (int j = 0; j < 4; j++) {
            float4 xa = sX[r0 * 5 + j];
            float4 xb = sX[r1 * 5 + j];
            float xas[4] = {xa.x, xa.y, xa.z, xa.w};
            float xbs[4] = {xb.x, xb.y, xb.z, xb.w};
#pragma unroll
            for (int i = 0; i < 4; i++) {
                int k = kt * 16 + j * 4 + i;
                const ulonglong2* wr = (const ulonglong2*)(sW1 + k * 4);
                u64 xpa, xpb;
                PACK2(xpa, xas[i]);
                PACK2(xpb, xbs[i]);
#pragma unroll
                for (int q = 0; q < 4; q++) {
                    ulonglong2 ww = wr[q];
                    FMA2(h0[2 * q],      xpa, ww.x);
                    FMA2(h0[2 * q + 1],  xpa, ww.y);
                    FMA2(h1v[2 * q],     xpb, ww.x);
                    FMA2(h1v[2 * q + 1], xpb, ww.y);
                }
            }
        }
    }

    float t0[HID], t1[HID];
#pragma unroll
    for (int q = 0; q < 8; q++) {
        unsigned lo, hi;
        UNPACK2(lo, hi, h0[q]);
        t0[2 * q] = ftanh(__uint_as_float(lo));
        t0[2 * q + 1] = ftanh(__uint_as_float(hi));
        UNPACK2(lo, hi, h1v[q]);
        t1[2 * q] = ftanh(__uint_as_float(lo));
        t1[2 * q + 1] = ftanh(__uint_as_float(hi));
    }

    // ---- layer 2 ----
    u64 a0[8], a1[8];
#pragma unroll
    for (int q = 0; q < 8; q++) { a0[q] = sb2[q]; a1[q] = sb2[q]; }
#pragma unroll
    for (int i = 0; i < HID; i++) {
        const ulonglong2* wr = (const ulonglong2*)(sW2 + i * 4);
        u64 p0, p1;
        PACK2(p0, t0[i]);
        PACK2(p1, t1[i]);
#pragma unroll
        for (int q = 0; q < 4; q++) {
            ulonglong2 ww = wr[q];
            FMA2(a0[2 * q],     p0, ww.x);
            FMA2(a0[2 * q + 1], p0, ww.y);
            FMA2(a1[2 * q],     p1, ww.x);
            FMA2(a1[2 * q + 1], p1, ww.y);
        }
    }
#pragma unroll
    for (int q = 0; q < 8; q++) {
        unsigned lo, hi;
        UNPACK2(lo, hi, a0[q]);
        t0[2 * q] = ftanh(__uint_as_float(lo));
        t0[2 * q + 1] = ftanh(__uint_as_float(hi));
        UNPACK2(lo, hi, a1[q]);
        t1[2 * q] = ftanh(__uint_as_float(lo));
        t1[2 * q + 1] = ftanh(__uint_as_float(hi));
    }

    // ---- layer 3 ----
#pragma unroll
    for (int q = 0; q < 8; q++) { a0[q] = sb3[q]; a1[q] = sb3[q]; }
#pragma unroll
    for (int i = 0; i < HID; i++) {
        const ulonglong2* wr = (const ulonglong2*)(sW3 + i * 4);
        u64 p0, p1;
        PACK2(p0, t0[i]);
        PACK2(p1, t1[i]);
#pragma unroll
        for (int q = 0; q < 4; q++) {
            ulonglong2 ww = wr[q];
            FMA2(a0[2 * q],     p0, ww.x);
            FMA2(a0[2 * q + 1], p0, ww.y);
            FMA2(a1[2 * q],     p1, ww.x);
            FMA2(a1[2 * q + 1], p1, ww.y);
        }
    }

    // tanh + contract with Wc -> scalar per node
    float s0 = 0.f, s1 = 0.f;
#pragma unroll
    for (int q = 0; q < 8; q++) {
        unsigned lo, hi;
        UNPACK2(lo, hi, a0[q]);
        s0 += ftanh(__uint_as_float(lo)) * sWc[2 * q];
        s0 += ftanh(__uint_as_float(hi)) * sWc[2 * q + 1];
        UNPACK2(lo, hi, a1[q]);
        s1 += ftanh(__uint_as_float(lo)) * sWc[2 * q];
        s1 += ftanh(__uint_as_float(hi)) * sWc[2 * q + 1];
    }
    // clamped duplicate writes carry identical values -> benign
    g_s[myN0] = s0;
    g_s[myN1] = s1;
}

// ------ K2: single edge pass: ud[src] += s[dst] + 2^24 (one REDG.64) ------
#define E_TPB 256
#define E_EPT 8
#define CNT_K 16777216.0   // 2^24

__global__ void __launch_bounds__(E_TPB) edge_kernel(
    const int* __restrict__ src, const int* __restrict__ dst, int e)
{
    long base = (long)(blockIdx.x * E_TPB + threadIdx.x) * E_EPT;
    if (base + E_EPT <= e) {
        int4 da = *(const int4*)(dst + base);
        int4 db = *(const int4*)(dst + base + 4);
        int4 sa = *(const int4*)(src + base);
        int4 sb = *(const int4*)(src + base + 4);
        float v0 = __ldg(&g_s[da.x]), v1 = __ldg(&g_s[da.y]);
        float v2 = __ldg(&g_s[da.z]), v3 = __ldg(&g_s[da.w]);
        float v4 = __ldg(&g_s[db.x]), v5 = __ldg(&g_s[db.y]);
        float v6 = __ldg(&g_s[db.z]), v7 = __ldg(&g_s[db.w]);
        atomicAdd(&g_ud[sa.x], (double)v0 + CNT_K);
        atomicAdd(&g_ud[sa.y], (double)v1 + CNT_K);
        atomicAdd(&g_ud[sa.z], (double)v2 + CNT_K);
        atomicAdd(&g_ud[sa.w], (double)v3 + CNT_K);
        atomicAdd(&g_ud[sb.x], (double)v4 + CNT_K);
        atomicAdd(&g_ud[sb.y], (double)v5 + CNT_K);
        atomicAdd(&g_ud[sb.z], (double)v6 + CNT_K);
        atomicAdd(&g_ud[sb.w], (double)v7 + CNT_K);
    } else {
        for (long i = base; i < e; i++)
            atomicAdd(&g_ud[src[i]], (double)__ldg(&g_s[dst[i]]) + CNT_K);
    }
}

// ------ K3: node pass: acc = sum_m u[m]/cnt[m]; sigmoid; reset state ------
#define N_TPB 256

__global__ void __launch_bounds__(N_TPB) node_kernel(
    const float* __restrict__ bc, float* __restrict__ out, int n, float inv_n)
{
    __shared__ float sRed[N_TPB / 32];
    int tid = threadIdx.x;
    int i = blockIdx.x * N_TPB + tid;
    float term = 0.f;

    if (i < n) {
        double v = g_ud[i];
        if (v != 0.0) {
            // cnt = round(v / 2^24); |sum(s)| < 2^23 so rounding recovers cnt exactly
            long long cnt = __double2ll_rn(v * (1.0 / CNT_K));
            float u = (float)(v - (double)cnt * CNT_K);
            term = u * __frcp_rn((float)cnt);
            g_ud[i] = 0.0;  // restore for next graph replay
        }
    }

    unsigned m = 0xffffffffu;
#pragma unroll
    for (int off = 16; off > 0; off >>= 1)
        term += __shfl_down_sync(m, term, off);
    if ((tid & 31) == 0) sRed[tid >> 5] = term;
    __syncthreads();

    if (tid == 0) {
        float v = 0.f;
#pragma unroll
        for (int wq = 0; wq < N_TPB / 32; wq++) v += sRed[wq];
        atomicAdd(&g_acc, v);
        __threadfence();
        unsigned ticket = atomicInc(&g_done, gridDim.x - 1);  // wraps to 0 on last
        if (ticket == gridDim.x - 1) {
            float z = g_acc * inv_n + bc[0];
            out[0] = 1.0f / (1.0f + __expf(-z));
            g_acc = 0.f;  // restore for next replay
        }
    }
}

extern "C" void kernel_launch(void* const* d_in, const int* in_sizes, int n_in,
                              void* d_out, int out_size) {
    const float* x    = (const float*)d_in[0];
    const int*   esrc = (const int*)  d_in[1];
    const int*   edst = (const int*)  d_in[2];
    const float* W1   = (const float*)d_in[3];
    const float* b1   = (const float*)d_in[4];
    const float* W2   = (const float*)d_in[5];
    const float* b2   = (const float*)d_in[6];
    const float* W3   = (const float*)d_in[7];
    const float* b3   = (const float*)d_in[8];
    const float* Wc   = (const float*)d_in[9];
    const float* bc   = (const float*)d_in[10];
    float* out = (float*)d_out;

    int n = in_sizes[0] / ND;
    int e = in_sizes[1];
    if (n > N_MAX) n = N_MAX;

    int nMlp = (n + NB - 1) / NB;
    mlp_kernel<<<nMlp, MLP_TPB>>>(x, W1, b1, W2, b2, W3, b3, Wc, n);

    int nEdge = (e + E_TPB * E_EPT - 1) / (E_TPB * E_EPT);
    edge_kernel<<<nEdge, E_TPB>>>(esrc, edst, e);

    int nNode = (n + N_TPB - 1) / N_TPB;
    node_kernel<<<nNode, N_TPB>>>(bc, out, n, 1.0f / (float)n);
}